// round 5
// baseline (speedup 1.0000x reference)
#include <cuda_runtime.h>
#include <cstdint>

#define B    4096
#define S    200
#define E    300
#define TAGS 2
#define EV4  75          // float4 per embedding row

#define NTH      512
#define BMG      8                   // rows per group
#define NG       4                   // groups per CTA
#define ROWS_CTA (BMG * NG)          // 32
#define NPAD     301                 // smem row stride (conflict-free)
#define NW       320                 // padded N (32 groups x 10)
#define BK       10
#define NKT      30                  // 300 / 10
#define TILE_F4  (BK * NW / 4)       // 800 float4 per W tile

// Pre-transposed, padded weights: wt[k*NW+n] = w[n*E+k]; pads stay 0 (zero-init)
__device__ float g_w1t[E * NW];
__device__ float g_w2t[E * NW];

__global__ __launch_bounds__(256) void transpose_pad2(
    const float* __restrict__ w1, const float* __restrict__ w2)
{
    const int idx = blockIdx.x * 256 + threadIdx.x;   // coalesced read over n*E+k
    if (idx >= E * E) return;
    const int n = idx / E, k = idx % E;
    if (blockIdx.y == 0) g_w1t[k * NW + n] = w1[idx];
    else                 g_w2t[k * NW + n] = w2[idx];
}

// ---------------- PTX helpers ----------------
__device__ __forceinline__ void cp16(uint32_t saddr, const void* g)
{ asm volatile("cp.async.cg.shared.global [%0], [%1], 16;" :: "r"(saddr), "l"(g)); }
__device__ __forceinline__ void cp_commit()
{ asm volatile("cp.async.commit_group;"); }

__device__ __forceinline__ void barw(int id)   // blocking wait, count 512
{ asm volatile("bar.sync %0, %1;" :: "r"(id), "n"(NTH) : "memory"); }
__device__ __forceinline__ void bara(int id)   // non-blocking arrive, count 512
{ asm volatile("bar.arrive %0, %1;" :: "r"(id), "n"(NTH) : "memory"); }
__device__ __forceinline__ void bar_cons()     // consumer-only barrier
{ asm volatile("bar.sync 5, 256;" ::: "memory"); }

#define FULLB(b)  (1 + (b))
#define EMPTYB(b) (3 + (b))

typedef unsigned long long u64;
__device__ __forceinline__ u64 pack2(float x)
{ u64 r; asm("mov.b64 %0, {%1, %1};" : "=l"(r) : "f"(x)); return r; }
__device__ __forceinline__ u64 fma2(u64 a, u64 b, u64 c)
{ u64 d; asm("fma.rn.f32x2 %0, %1, %2, %3;" : "=l"(d) : "l"(a), "l"(b), "l"(c)); return d; }
__device__ __forceinline__ float lo32(u64 v) { return __uint_as_float((uint32_t)(v & 0xffffffffull)); }
__device__ __forceinline__ float hi32(u64 v) { return __uint_as_float((uint32_t)(v >> 32)); }

// ---------------------------------------------------------------------------
// Consumer GEMM: acc2[j] (f32x2) += s_a[m][k] * Wt[k][n0+2j(+1)], k = 0..299.
// Wt pretransposed [300][320]. 256 consumer threads. cp.async double buffer.
// ---------------------------------------------------------------------------
__device__ __forceinline__ void gemmT(
    const float* __restrict__ Wt,
    const float* __restrict__ s_a,
    float (*s_w)[BK * NW],
    int m, int n0, int ctid, u64 acc2[5])
{
#pragma unroll
    for (int j = 0; j < 5; ++j) acc2[j] = 0ull;

    const uint32_t sb0 = (uint32_t)__cvta_generic_to_shared(&s_w[0][0]);
    const uint32_t sb1 = (uint32_t)__cvta_generic_to_shared(&s_w[1][0]);

#pragma unroll
    for (int i = 0; i < 4; ++i) {
        const int idx = ctid + i * 256;
        if (idx < TILE_F4) cp16(sb0 + idx * 16, Wt + idx * 4);
    }
    cp_commit();

    for (int kt = 0; kt < NKT; ++kt) {
        if (kt + 1 < NKT) {
            const uint32_t dst = ((kt + 1) & 1) ? sb1 : sb0;
            const float* src = Wt + (kt + 1) * BK * NW;
#pragma unroll
            for (int i = 0; i < 4; ++i) {
                const int idx = ctid + i * 256;
                if (idx < TILE_F4) cp16(dst + idx * 16, src + idx * 4);
            }
            cp_commit();
            asm volatile("cp.async.wait_group 1;");
        } else {
            asm volatile("cp.async.wait_group 0;");
        }
        bar_cons();                      // tile kt visible (also orders s_a stores)

        const float* wb = s_w[kt & 1];
        const int kb = kt * BK;
#pragma unroll
        for (int kk = 0; kk < BK; ++kk) {
            const u64 a2 = pack2(s_a[m * NPAD + kb + kk]);
            const u64* wr = (const u64*)(wb + kk * NW + n0);   // n0 even -> 8B aligned
#pragma unroll
            for (int j = 0; j < 5; ++j)
                acc2[j] = fma2(a2, wr[j], acc2[j]);
        }
        bar_cons();                      // buffer free for refill
    }
}

// ---------------------------------------------------------------------------
// Warp-specialized fused kernel: producers gather+pool, consumers 2xGEMM+head.
// ---------------------------------------------------------------------------
__global__ __launch_bounds__(NTH, 2) void fused_ws(
    const int*   __restrict__ x,
    const float* __restrict__ emb,
    const float* __restrict__ w3,
    float*       __restrict__ out)
{
    __shared__ float s_a[2][BMG * NPAD];    // 19264 B
    __shared__ float s_w[2][BK * NW];       // 25600 B
    __shared__ float s_w3[TAGS * NW];       //  2560 B   (total 47424 < 48K)

    float* s_part = &s_w[0][0];             // alias: safe (see barriers below)

    const int tid = threadIdx.x;
    const int b0  = blockIdx.x * ROWS_CTA;

    for (int i = tid; i < TAGS * NW; i += NTH) {
        const int t = i / NW, n = i % NW;
        s_w3[i] = (n < E) ? w3[t * E + n] : 0.0f;
    }
    __syncthreads();

    if (tid < 256) {
        // ======================= PRODUCERS (warps 0-7) =======================
        const int p = tid >> 5, lane = tid & 31;
        const float4* __restrict__ ev = (const float4*)emb;
        const bool has2 = lane < (EV4 - 64);     // lanes 0..10 own slot lane+64

        for (int i = 0; i < NG; ++i) {
            const int b = i & 1;
            if (i >= 2) barw(EMPTYB(b));

            const int row = b0 + i * BMG + p;
            // stage this row's 200 token ids in registers (7 per lane)
            int myids[7];
#pragma unroll
            for (int u = 0; u < 7; ++u) {
                const int t = u * 32 + lane;
                myids[u] = (t < S) ? x[row * S + t] : 0;
            }

            float4 a0 = {0,0,0,0}, a1 = {0,0,0,0}, a2 = {0,0,0,0};
#pragma unroll
            for (int u = 0; u < 7; ++u) {
                const int tmax = (u < 6) ? 32 : (S - 192);   // 32 or 8
#pragma unroll 8
                for (int tt = 0; tt < tmax; ++tt) {
                    const int base = __shfl_sync(0xffffffffu, myids[u], tt) * EV4;
                    float4 v0 = __ldg(ev + base + lane);
                    float4 v1 = __ldg(ev + base + lane + 32);
                    a0.x += v0.x; a0.y += v0.y; a0.z += v0.z; a0.w += v0.w;
                    a1.x += v1.x; a1.y += v1.y; a1.z += v1.z; a1.w += v1.w;
                    if (has2) {
                        float4 v2 = __ldg(ev + base + lane + 64);
                        a2.x += v2.x; a2.y += v2.y; a2.z += v2.z; a2.w += v2.w;
                    }
                }
            }
            const float sc = 1.0f / (float)S;
            float* pr = &s_a[b][p * NPAD];
            const int d0 = 4 * lane, d1 = 4 * (lane + 32), d2 = 4 * (lane + 64);
            pr[d0+0]=a0.x*sc; pr[d0+1]=a0.y*sc; pr[d0+2]=a0.z*sc; pr[d0+3]=a0.w*sc;
            pr[d1+0]=a1.x*sc; pr[d1+1]=a1.y*sc; pr[d1+2]=a1.z*sc; pr[d1+3]=a1.w*sc;
            if (has2) { pr[d2+0]=a2.x*sc; pr[d2+1]=a2.y*sc; pr[d2+2]=a2.z*sc; pr[d2+3]=a2.w*sc; }

            __threadfence_block();
            bara(FULLB(b));
        }
    } else {
        // ======================= CONSUMERS (warps 8-15) ======================
        const int ctid = tid - 256;
        const int m  = ctid & 7;
        const int g  = ctid >> 3;
        const int n0 = g * 10;

        for (int i = 0; i < NG; ++i) {
            const int b = i & 1;
            barw(FULLB(b));

            u64 acc2[5];
            // layer 1
            gemmT(g_w1t, s_a[b], s_w, m, n0, ctid, acc2);
            // relu -> h1 in place (reads all done: gemmT ends with bar_cons)
#pragma unroll
            for (int j = 0; j < 5; ++j) {
                const int n = n0 + 2 * j;
                if (n     < E) s_a[b][m * NPAD + n]     = fmaxf(lo32(acc2[j]), 0.0f);
                if (n + 1 < E) s_a[b][m * NPAD + n + 1] = fmaxf(hi32(acc2[j]), 0.0f);
            }
            // layer 2 (first bar_cons inside orders the h1 stores)
            gemmT(g_w2t, s_a[b], s_w, m, n0, ctid, acc2);
            bara(EMPTYB(b));                 // producers may refill s_a[b]

            // fused head
            float s0 = 0.0f, s1 = 0.0f;
#pragma unroll
            for (int j = 0; j < 5; ++j) {
                const float lo = fmaxf(lo32(acc2[j]), 0.0f);
                const float hi = fmaxf(hi32(acc2[j]), 0.0f);
                s0 = fmaf(lo, s_w3[n0 + 2*j],      s0);
                s0 = fmaf(hi, s_w3[n0 + 2*j + 1],  s0);
                s1 = fmaf(lo, s_w3[NW + n0 + 2*j],     s1);
                s1 = fmaf(hi, s_w3[NW + n0 + 2*j + 1], s1);
            }
            s_part[(m * 32 + g) * 2 + 0] = s0;
            s_part[(m * 32 + g) * 2 + 1] = s1;
            bar_cons();
            if (ctid < BMG * TAGS) {
                const int mm = ctid >> 1, t = ctid & 1;
                float s = 0.0f;
#pragma unroll
                for (int gg = 0; gg < 32; ++gg)
                    s += s_part[(mm * 32 + gg) * 2 + t];
                out[(b0 + i * BMG + mm) * TAGS + t] = s;
            }
            bar_cons();   // s_part reads done before next group's cp.async reuses s_w[0]
        }
    }
}

// ---------------------------------------------------------------------------
// Launch
// ---------------------------------------------------------------------------
extern "C" void kernel_launch(void* const* d_in, const int* in_sizes, int n_in,
                              void* d_out, int out_size)
{
    const int*   x   = (const int*)d_in[0];
    const float* emb = (const float*)d_in[1];
    const float* w1  = (const float*)d_in[2];
    const float* w2  = (const float*)d_in[3];
    const float* w3  = (const float*)d_in[4];
    float* out = (float*)d_out;

    dim3 tgrid((E * E + 255) / 256, 2);
    transpose_pad2<<<tgrid, 256>>>(w1, w2);

    fused_ws<<<B / ROWS_CTA, NTH>>>(x, emb, w3, out);
}

// round 7
// speedup vs baseline: 1.3928x; 1.3928x over previous
#include <cuda_runtime.h>
#include <cstdint>

#define B    4096
#define S    200
#define E    300
#define TAGS 2
#define EV4  75          // float4 per embedding row

#define PCTA 512         // pool CTAs (8 rows each)
#define TCTA 120         // transpose CTAs (run concurrently)

#define GM   16          // rows per GEMM CTA
#define NT   256
#define NPAD 301         // conflict-free smem row stride (scalar access only!)
#define NW   320         // padded N: 16 groups x 20
#define BK   10
#define NKT  30          // 300/10
#define TILE_F4 (BK * NW / 4)   // 800

// device scratch
__device__ float g_pooled[B * E];
__device__ float g_w1t[E * NW];   // wt[k*NW+n] = w[n*E+k]; pads stay 0 (zero-init)
__device__ float g_w2t[E * NW];

// ---------------- PTX helpers ----------------
__device__ __forceinline__ void cp16(uint32_t saddr, const void* g)
{ asm volatile("cp.async.cg.shared.global [%0], [%1], 16;" :: "r"(saddr), "l"(g)); }
__device__ __forceinline__ void cp_commit()
{ asm volatile("cp.async.commit_group;"); }

typedef unsigned long long u64;
__device__ __forceinline__ u64 pack2(float x)
{ u64 r; asm("mov.b64 %0, {%1, %1};" : "=l"(r) : "f"(x)); return r; }
__device__ __forceinline__ u64 fma2(u64 a, u64 b, u64 c)
{ u64 d; asm("fma.rn.f32x2 %0, %1, %2, %3;" : "=l"(d) : "l"(a), "l"(b), "l"(c)); return d; }
__device__ __forceinline__ float lo32(u64 v) { return __uint_as_float((uint32_t)(v & 0xffffffffull)); }
__device__ __forceinline__ float hi32(u64 v) { return __uint_as_float((uint32_t)(v >> 32)); }

// ---------------------------------------------------------------------------
// Kernel 1: CTAs [0,512): gather+mean-pool, warp-per-row.
//           CTAs [512,512+120): transpose+pad W1,W2 (hidden under the gather).
// ---------------------------------------------------------------------------
__global__ __launch_bounds__(NT) void pool_and_prep(
    const int*   __restrict__ x,
    const float* __restrict__ emb,
    const float* __restrict__ w1,
    const float* __restrict__ w2)
{
    if (blockIdx.x >= PCTA) {
        // ---- transpose/pad (grid-stride over both matrices) ----
        const int total = E * E;
        const int start = (blockIdx.x - PCTA) * NT + threadIdx.x;
        const int step  = TCTA * NT;
        for (int idx = start; idx < 2 * total; idx += step) {
            const int sel = idx / total;            // 0 -> w1, 1 -> w2
            const int e   = idx - sel * total;      // coalesced over n*E+k
            const int n = e / E, k = e % E;
            const float v = sel ? w2[e] : w1[e];
            if (sel) g_w2t[k * NW + n] = v;
            else     g_w1t[k * NW + n] = v;
        }
        return;
    }

    // ---- gather + mean pool: 8 warps, one row each ----
    __shared__ int s_ids[8 * S];
    const int b0 = blockIdx.x * 8;
    {
        const int4* src = (const int4*)(x + b0 * S);
        int4* dst = (int4*)s_ids;
#pragma unroll
        for (int i = 0; i < 2; ++i) {
            const int idx = threadIdx.x + i * NT;
            if (idx < 8 * S / 4) dst[idx] = src[idx];
        }
    }
    __syncthreads();

    const int w = threadIdx.x >> 5, lane = threadIdx.x & 31;
    const bool has2 = lane < (EV4 - 64);            // lanes 0..10 own slot lane+64
    const float4* __restrict__ ev = (const float4*)emb;
    const int* __restrict__ rid = s_ids + w * S;

    float4 a0 = {0,0,0,0}, a1 = {0,0,0,0}, a2 = {0,0,0,0};
#pragma unroll 4
    for (int t = 0; t < S; ++t) {
        const int base = rid[t] * EV4;              // <= 37.5M, fits int32
        float4 v0 = __ldg(ev + base + lane);
        float4 v1 = __ldg(ev + base + lane + 32);
        a0.x += v0.x; a0.y += v0.y; a0.z += v0.z; a0.w += v0.w;
        a1.x += v1.x; a1.y += v1.y; a1.z += v1.z; a1.w += v1.w;
        if (has2) {
            float4 v2 = __ldg(ev + base + lane + 64);
            a2.x += v2.x; a2.y += v2.y; a2.z += v2.z; a2.w += v2.w;
        }
    }
    const float sc = 1.0f / (float)S;
    // g_pooled rows are 1200B -> float4-aligned (global)
    float4* p = (float4*)(g_pooled + (b0 + w) * E);
    p[lane]      = make_float4(a0.x*sc, a0.y*sc, a0.z*sc, a0.w*sc);
    p[lane + 32] = make_float4(a1.x*sc, a1.y*sc, a1.z*sc, a1.w*sc);
    if (has2)
        p[lane + 64] = make_float4(a2.x*sc, a2.y*sc, a2.z*sc, a2.w*sc);
}

// ---------------------------------------------------------------------------
// One layer: acc2[j] += a[m][k] * Wt[k][n0+2j..], k = 0..299 (f32x2 FMAs).
// Wt pretransposed [300][NW]. cp.async double-buffered tiles. All 256 threads.
// ---------------------------------------------------------------------------
__device__ __forceinline__ void gemmT(
    const float* __restrict__ Wt,
    const float* __restrict__ s_a,
    float (*s_w)[BK * NW],
    int m, int n0, int tid, u64 acc2[10])
{
#pragma unroll
    for (int j = 0; j < 10; ++j) acc2[j] = 0ull;

    const uint32_t sb0 = (uint32_t)__cvta_generic_to_shared(&s_w[0][0]);
    const uint32_t sb1 = (uint32_t)__cvta_generic_to_shared(&s_w[1][0]);

#pragma unroll
    for (int i = 0; i < 4; ++i) {
        const int idx = tid + i * NT;
        if (idx < TILE_F4) cp16(sb0 + idx * 16, Wt + idx * 4);
    }
    cp_commit();

    for (int kt = 0; kt < NKT; ++kt) {
        if (kt + 1 < NKT) {
            const uint32_t dst = ((kt + 1) & 1) ? sb1 : sb0;
            const float* src = Wt + (kt + 1) * BK * NW;
#pragma unroll
            for (int i = 0; i < 4; ++i) {
                const int idx = tid + i * NT;
                if (idx < TILE_F4) cp16(dst + idx * 16, src + idx * 4);
            }
            cp_commit();
            asm volatile("cp.async.wait_group 1;");
        } else {
            asm volatile("cp.async.wait_group 0;");
        }
        __syncthreads();

        const float* wb = s_w[kt & 1];
        const int kb = kt * BK;
#pragma unroll
        for (int kk = 0; kk < BK; ++kk) {
            const u64 a2 = pack2(s_a[m * NPAD + kb + kk]);   // scalar LDS (any align)
            // s_w base 16B-aligned; offset (kk*NW + n0)*4 = kk*1280 + g*80 bytes -> 16B-aligned
            const ulonglong2* wr = (const ulonglong2*)(wb + kk * NW + n0);
#pragma unroll
            for (int j = 0; j < 5; ++j) {
                const ulonglong2 wv = wr[j];
                acc2[2*j + 0] = fma2(a2, wv.x, acc2[2*j + 0]);
                acc2[2*j + 1] = fma2(a2, wv.y, acc2[2*j + 1]);
            }
        }
        __syncthreads();
    }
}

// ---------------------------------------------------------------------------
// Kernel 2: 16 rows/CTA: relu(relu(pooled W1^T) W2^T) W3^T -> out
// ---------------------------------------------------------------------------
__global__ __launch_bounds__(NT, 4) void gemm_head(
    const float* __restrict__ pooled,
    const float* __restrict__ w3,
    float*       __restrict__ out)
{
    __shared__ float s_a[GM * NPAD];        // 19264 B
    __shared__ float s_w[2][BK * NW];       // 25600 B
    __shared__ float s_w3[TAGS * NW];       //  2560 B  (total 47424 < 48K)
    float* s_part = &s_w[0][0];             // alias after last wait_group 0

    const int tid = threadIdx.x;
    const int b0  = blockIdx.x * GM;

    // stage pooled rows (vector global load, SCALAR smem stores: NPAD rows are
    // only 4B-aligned) + padded w3
    {
        const float4* src = (const float4*)(pooled + b0 * E);
#pragma unroll
        for (int i = 0; i < 5; ++i) {
            const int idx = tid + i * NT;    // 0..1199 float4
            if (idx < GM * E / 4) {
                const int m = idx / EV4, s = idx - m * EV4;
                const float4 v = src[idx];
                float* dst = &s_a[m * NPAD + s * 4];
                dst[0] = v.x; dst[1] = v.y; dst[2] = v.z; dst[3] = v.w;
            }
        }
#pragma unroll
        for (int i = 0; i < 3; ++i) {
            const int idx = tid + i * NT;
            if (idx < TAGS * NW) {
                const int t = idx / NW, n = idx % NW;
                s_w3[idx] = (n < E) ? w3[t * E + n] : 0.0f;
            }
        }
    }
    // first __syncthreads inside gemmT fences the staging stores

    const int m  = tid & 15;                // m fast -> 16-way w broadcast in warp
    const int g  = tid >> 4;                // 0..15
    const int n0 = g * 20;

    u64 acc2[10];

    // layer 1
    gemmT(g_w1t, s_a, s_w, m, n0, tid, acc2);
    // relu -> h1 in place (all s_a reads done: gemmT ends with __syncthreads)
#pragma unroll
    for (int j = 0; j < 10; ++j) {
        const int n = n0 + 2 * j;
        if (n     < E) s_a[m * NPAD + n]     = fmaxf(lo32(acc2[j]), 0.0f);
        if (n + 1 < E) s_a[m * NPAD + n + 1] = fmaxf(hi32(acc2[j]), 0.0f);
    }
    // layer 2 (+fused head); first sync inside orders h1 stores
    gemmT(g_w2t, s_a, s_w, m, n0, tid, acc2);

    float s0 = 0.0f, s1 = 0.0f;
#pragma unroll
    for (int j = 0; j < 10; ++j) {
        const float lo = fmaxf(lo32(acc2[j]), 0.0f);    // pad cols: w=0 -> acc=0
        const float hi = fmaxf(hi32(acc2[j]), 0.0f);
        s0 = fmaf(lo, s_w3[n0 + 2*j],          s0);
        s0 = fmaf(hi, s_w3[n0 + 2*j + 1],      s0);
        s1 = fmaf(lo, s_w3[NW + n0 + 2*j],     s1);
        s1 = fmaf(hi, s_w3[NW + n0 + 2*j + 1], s1);
    }
    s_part[(m * 16 + g) * 2 + 0] = s0;       // safe: all cp.async drained
    s_part[(m * 16 + g) * 2 + 1] = s1;
    __syncthreads();

    if (tid < GM * TAGS) {
        const int mm = tid >> 1, t = tid & 1;
        float s = 0.0f;
#pragma unroll
        for (int gg = 0; gg < 16; ++gg)
            s += s_part[(mm * 16 + gg) * 2 + t];
        out[(b0 + mm) * TAGS + t] = s;
    }
}

// ---------------------------------------------------------------------------
// Launch
// ---------------------------------------------------------------------------
extern "C" void kernel_launch(void* const* d_in, const int* in_sizes, int n_in,
                              void* d_out, int out_size)
{
    const int*   x   = (const int*)d_in[0];
    const float* emb = (const float*)d_in[1];
    const float* w1  = (const float*)d_in[2];
    const float* w2  = (const float*)d_in[3];
    const float* w3  = (const float*)d_in[4];
    float* out = (float*)d_out;

    float* pooled; cudaGetSymbolAddress((void**)&pooled, g_pooled);

    pool_and_prep<<<PCTA + TCTA, NT>>>(x, emb, w1, w2);
    gemm_head<<<B / GM, NT>>>(pooled, w3, out);
}

// round 10
// speedup vs baseline: 1.3953x; 1.0018x over previous
#include <cuda_runtime.h>
#include <cstdint>

#define B    4096
#define S    200
#define E    300
#define TAGS 2
#define EV4  75          // float4 per embedding row

#define PCTA 512         // pool CTAs (8 rows each)
#define TCTA 120         // transpose CTAs (run concurrently)

#define GM   8           // rows per GEMM CTA
#define NT   128         // threads per GEMM CTA
#define NPAD 301         // conflict-free smem row stride (SCALAR access only)
#define NW   320         // padded N: 16 groups x 20
#define BK   10
#define NKT  30          // 300/10
#define TILE_F  (BK * NW)        // 3200 floats per tile
#define TILE_F4 (TILE_F / 4)     // 800 float4

// device scratch
__device__ float g_pooled[B * E];
__device__ float g_w1t[E * NW];   // wt[k*NW+n] = w[n*E+k]; pads stay 0 (zero-init)
__device__ float g_w2t[E * NW];

// ---------------- PTX helpers ----------------
__device__ __forceinline__ void cp16(uint32_t saddr, const void* g)
{ asm volatile("cp.async.cg.shared.global [%0], [%1], 16;" :: "r"(saddr), "l"(g)); }
__device__ __forceinline__ void cp_commit()
{ asm volatile("cp.async.commit_group;"); }

typedef unsigned long long u64;
__device__ __forceinline__ u64 pack2(float x)
{ u64 r; asm("mov.b64 %0, {%1, %1};" : "=l"(r) : "f"(x)); return r; }
__device__ __forceinline__ u64 fma2(u64 a, u64 b, u64 c)
{ u64 d; asm("fma.rn.f32x2 %0, %1, %2, %3;" : "=l"(d) : "l"(a), "l"(b), "l"(c)); return d; }
__device__ __forceinline__ float lo32(u64 v) { return __uint_as_float((uint32_t)(v & 0xffffffffull)); }
__device__ __forceinline__ float hi32(u64 v) { return __uint_as_float((uint32_t)(v >> 32)); }

// ---------------------------------------------------------------------------
// Kernel 1: CTAs [0,512): gather+mean-pool, warp-per-row.
//           CTAs [512,512+120): transpose+pad W1,W2 (hidden under the gather).
// ---------------------------------------------------------------------------
__global__ __launch_bounds__(256) void pool_and_prep(
    const int*   __restrict__ x,
    const float* __restrict__ emb,
    const float* __restrict__ w1,
    const float* __restrict__ w2)
{
    if (blockIdx.x >= PCTA) {
        const int total = E * E;
        const int start = (blockIdx.x - PCTA) * 256 + threadIdx.x;
        const int step  = TCTA * 256;
        for (int idx = start; idx < 2 * total; idx += step) {
            const int sel = idx / total;            // 0 -> w1, 1 -> w2
            const int e   = idx - sel * total;      // coalesced over n*E+k
            const int n = e / E, k = e % E;
            const float v = sel ? w2[e] : w1[e];
            if (sel) g_w2t[k * NW + n] = v;
            else     g_w1t[k * NW + n] = v;
        }
        return;
    }

    __shared__ int s_ids[8 * S];
    const int b0 = blockIdx.x * 8;
    {
        const int4* src = (const int4*)(x + b0 * S);
        int4* dst = (int4*)s_ids;
#pragma unroll
        for (int i = 0; i < 2; ++i) {
            const int idx = threadIdx.x + i * 256;
            if (idx < 8 * S / 4) dst[idx] = src[idx];
        }
    }
    __syncthreads();

    const int w = threadIdx.x >> 5, lane = threadIdx.x & 31;
    const bool has2 = lane < (EV4 - 64);            // lanes 0..10 own slot lane+64
    const float4* __restrict__ ev = (const float4*)emb;
    const int* __restrict__ rid = s_ids + w * S;

    float4 a0 = {0,0,0,0}, a1 = {0,0,0,0}, a2 = {0,0,0,0};
#pragma unroll 4
    for (int t = 0; t < S; ++t) {
        const int base = rid[t] * EV4;              // <= 37.5M, fits int32
        float4 v0 = __ldg(ev + base + lane);
        float4 v1 = __ldg(ev + base + lane + 32);
        a0.x += v0.x; a0.y += v0.y; a0.z += v0.z; a0.w += v0.w;
        a1.x += v1.x; a1.y += v1.y; a1.z += v1.z; a1.w += v1.w;
        if (has2) {
            float4 v2 = __ldg(ev + base + lane + 64);
            a2.x += v2.x; a2.y += v2.y; a2.z += v2.z; a2.w += v2.w;
        }
    }
    const float sc = 1.0f / (float)S;
    float4* p = (float4*)(g_pooled + (b0 + w) * E);
    p[lane]      = make_float4(a0.x*sc, a0.y*sc, a0.z*sc, a0.w*sc);
    p[lane + 32] = make_float4(a1.x*sc, a1.y*sc, a1.z*sc, a1.w*sc);
    if (has2)
        p[lane + 64] = make_float4(a2.x*sc, a2.y*sc, a2.z*sc, a2.w*sc);
}

// ---------------------------------------------------------------------------
// One layer: acc2[j] += a[m][k] * Wt[k][n0+2j..], k = 0..299 (f32x2 FMAs).
// Wt pretransposed [300][NW]. PROVEN 2-buffer pipeline, 2 syncs per tile:
//   issue kt+1; commit; wait_group (local) ; __syncthreads (global visibility)
//   compute kt ; __syncthreads (WAR: buffer free before refill)
// All NT threads must call (uniform).
// ---------------------------------------------------------------------------
__device__ __forceinline__ void gemmT(
    const float* __restrict__ Wt,
    const float* __restrict__ s_a,
    float (*s_w)[TILE_F],
    int m, int n0, int tid, u64 acc2[10])
{
#pragma unroll
    for (int j = 0; j < 10; ++j) acc2[j] = 0ull;

    const uint32_t sb0 = (uint32_t)__cvta_generic_to_shared(&s_w[0][0]);
    const uint32_t sb1 = (uint32_t)__cvta_generic_to_shared(&s_w[1][0]);

    // prologue: tile 0 -> buf 0
#pragma unroll
    for (int i = 0; i < 7; ++i) {
        const int idx = tid + i * NT;
        if (idx < TILE_F4) cp16(sb0 + idx * 16, Wt + idx * 4);
    }
    cp_commit();

    for (int kt = 0; kt < NKT; ++kt) {
        if (kt + 1 < NKT) {
            const uint32_t dst = ((kt + 1) & 1) ? sb1 : sb0;
            const float* src = Wt + (kt + 1) * TILE_F;
#pragma unroll
            for (int i = 0; i < 7; ++i) {
                const int idx = tid + i * NT;
                if (idx < TILE_F4) cp16(dst + idx * 16, src + idx * 4);
            }
            cp_commit();
            asm volatile("cp.async.wait_group 1;");   // my tile-kt copies done
        } else {
            asm volatile("cp.async.wait_group 0;");
        }
        __syncthreads();              // ALL threads' tile-kt copies visible

        const float* wb = s_w[kt & 1];
        const int kb = kt * BK;
#pragma unroll
        for (int kk = 0; kk < BK; ++kk) {
            const u64 a2 = pack2(s_a[m * NPAD + kb + kk]);   // scalar LDS
            // offset (kk*NW + n0) floats = kk*1280 + 80g bytes -> 16B aligned
            const ulonglong2* wr = (const ulonglong2*)(wb + kk * NW + n0);
#pragma unroll
            for (int j = 0; j < 5; ++j) {
                const ulonglong2 wv = wr[j];
                acc2[2*j + 0] = fma2(a2, wv.x, acc2[2*j + 0]);
                acc2[2*j + 1] = fma2(a2, wv.y, acc2[2*j + 1]);
            }
        }
        __syncthreads();              // buf kt free before next refill
    }
}

// ---------------------------------------------------------------------------
// Kernel 2: 8 rows/CTA, 128 threads, grid 512:
//   relu(relu(pooled W1^T) W2^T) W3^T -> out
// ---------------------------------------------------------------------------
__global__ __launch_bounds__(NT) void gemm_head(
    const float* __restrict__ pooled,
    const float* __restrict__ w3,
    float*       __restrict__ out)
{
    __shared__ float s_w[2][TILE_F];        // 25600 B
    __shared__ float s_a[GM * NPAD];        //  9632 B
    __shared__ float s_w3[TAGS * NW];       //  2560 B  (total 37792 B)
    float* s_part = &s_w[0][0];             // alias after all cp.async drained

    const int tid = threadIdx.x;
    const int b0  = blockIdx.x * GM;

    // stage pooled rows (vector gmem load, SCALAR smem stores: NPAD rows only
    // 4B-aligned) + padded w3
    {
        const float4* src = (const float4*)(pooled + b0 * E);
#pragma unroll
        for (int i = 0; i < 5; ++i) {
            const int idx = tid + i * NT;        // 0..599 float4
            if (idx < GM * E / 4) {
                const int m = idx / EV4, s = idx - m * EV4;
                const float4 v = src[idx];
                float* dst = &s_a[m * NPAD + s * 4];
                dst[0] = v.x; dst[1] = v.y; dst[2] = v.z; dst[3] = v.w;
            }
        }
#pragma unroll
        for (int i = 0; i < 5; ++i) {
            const int idx = tid + i * NT;
            if (idx < TAGS * NW) {
                const int t = idx / NW, n = idx % NW;
                s_w3[idx] = (n < E) ? w3[t * E + n] : 0.0f;
            }
        }
    }
    // first __syncthreads inside gemmT (post-wait) fences the staging stores

    const int m  = tid & 7;             // m fast -> w broadcast within warp
    const int g  = tid >> 3;            // 0..15
    const int n0 = g * 20;

    u64 acc2[10];

    // layer 1
    gemmT(g_w1t, s_a, s_w, m, n0, tid, acc2);
    // gemmT ends with __syncthreads: all layer-1 reads of s_a complete
#pragma unroll
    for (int j = 0; j < 10; ++j) {
        const int n = n0 + 2 * j;
        if (n     < E) s_a[m * NPAD + n]     = fmaxf(lo32(acc2[j]), 0.0f);
        if (n + 1 < E) s_a[m * NPAD + n + 1] = fmaxf(hi32(acc2[j]), 0.0f);
    }
    // layer 2 (+fused head); first post-wait sync inside orders the h1 stores
    gemmT(g_w2t, s_a, s_w, m, n0, tid, acc2);

    float s0 = 0.0f, s1 = 0.0f;
#pragma unroll
    for (int j = 0; j < 10; ++j) {
        const float lo = fmaxf(lo32(acc2[j]), 0.0f);    // pad cols: w=0 -> acc=0
        const float hi = fmaxf(hi32(acc2[j]), 0.0f);
        s0 = fmaf(lo, s_w3[n0 + 2*j],          s0);
        s0 = fmaf(hi, s_w3[n0 + 2*j + 1],      s0);
        s1 = fmaf(lo, s_w3[NW + n0 + 2*j],     s1);
        s1 = fmaf(hi, s_w3[NW + n0 + 2*j + 1], s1);
    }
    // gemmT's trailing __syncthreads: all compute done, all cp.async drained
    s_part[(m * 16 + g) * 2 + 0] = s0;
    s_part[(m * 16 + g) * 2 + 1] = s1;
    __syncthreads();

    if (tid < GM * TAGS) {
        const int mm = tid >> 1, t = tid & 1;
        float s = 0.0f;
#pragma unroll
        for (int gg = 0; gg < 16; ++gg)
            s += s_part[(mm * 16 + gg) * 2 + t];
        out[(b0 + mm) * TAGS + t] = s;
    }
}

// ---------------------------------------------------------------------------
// Launch
// ---------------------------------------------------------------------------
extern "C" void kernel_launch(void* const* d_in, const int* in_sizes, int n_in,
                              void* d_out, int out_size)
{
    const int*   x   = (const int*)d_in[0];
    const float* emb = (const float*)d_in[1];
    const float* w1  = (const float*)d_in[2];
    const float* w2  = (const float*)d_in[3];
    const float* w3  = (const float*)d_in[4];
    float* out = (float*)d_out;

    float* pooled; cudaGetSymbolAddress((void**)&pooled, g_pooled);

    pool_and_prep<<<PCTA + TCTA, 256>>>(x, emb, w1, w2);
    gemm_head<<<B / GM, NT>>>(pooled, w3, out);
}

// round 11
// speedup vs baseline: 1.5715x; 1.1263x over previous
#include <cuda_runtime.h>
#include <cstdint>

#define B    4096
#define S    200
#define E    300
#define TAGS 2
#define EV4  75          // float4 per embedding row

#define PCTA 512         // pool CTAs (8 rows each)
#define TCTA 120         // transpose CTAs (run concurrently)

#define GM   16          // rows per GEMM CTA
#define NT   128         // threads per GEMM CTA
#define NPAD 301         // conflict-free smem row stride (SCALAR access only)
#define NW   320         // padded N: 16 groups x 20
#define BK   10
#define NKT  30          // 300/10
#define TILE_F  (BK * NW)        // 3200 floats per tile
#define TILE_F4 (TILE_F / 4)     // 800 float4

// device scratch
__device__ float g_pooled[B * E];
__device__ float g_w1t[E * NW];   // wt[k*NW+n] = w[n*E+k]; pads stay 0 (zero-init)
__device__ float g_w2t[E * NW];

// ---------------- PTX helpers ----------------
__device__ __forceinline__ void cp16(uint32_t saddr, const void* g)
{ asm volatile("cp.async.cg.shared.global [%0], [%1], 16;" :: "r"(saddr), "l"(g)); }
__device__ __forceinline__ void cp_commit()
{ asm volatile("cp.async.commit_group;"); }

typedef unsigned long long u64;
__device__ __forceinline__ u64 pack2(float x)
{ u64 r; asm("mov.b64 %0, {%1, %1};" : "=l"(r) : "f"(x)); return r; }
__device__ __forceinline__ u64 fma2(u64 a, u64 b, u64 c)
{ u64 d; asm("fma.rn.f32x2 %0, %1, %2, %3;" : "=l"(d) : "l"(a), "l"(b), "l"(c)); return d; }
__device__ __forceinline__ float lo32(u64 v) { return __uint_as_float((uint32_t)(v & 0xffffffffull)); }
__device__ __forceinline__ float hi32(u64 v) { return __uint_as_float((uint32_t)(v >> 32)); }

// ---------------------------------------------------------------------------
// Kernel 1: CTAs [0,512): gather+mean-pool, warp-per-row.
//           CTAs [512,512+120): transpose+pad W1,W2 (hidden under the gather).
// ---------------------------------------------------------------------------
__global__ __launch_bounds__(256) void pool_and_prep(
    const int*   __restrict__ x,
    const float* __restrict__ emb,
    const float* __restrict__ w1,
    const float* __restrict__ w2)
{
    if (blockIdx.x >= PCTA) {
        const int total = E * E;
        const int start = (blockIdx.x - PCTA) * 256 + threadIdx.x;
        const int step  = TCTA * 256;
        for (int idx = start; idx < 2 * total; idx += step) {
            const int sel = idx / total;            // 0 -> w1, 1 -> w2
            const int e   = idx - sel * total;      // coalesced over n*E+k
            const int n = e / E, k = e % E;
            const float v = sel ? w2[e] : w1[e];
            if (sel) g_w2t[k * NW + n] = v;
            else     g_w1t[k * NW + n] = v;
        }
        return;
    }

    __shared__ int s_ids[8 * S];
    const int b0 = blockIdx.x * 8;
    {
        const int4* src = (const int4*)(x + b0 * S);
        int4* dst = (int4*)s_ids;
#pragma unroll
        for (int i = 0; i < 2; ++i) {
            const int idx = threadIdx.x + i * 256;
            if (idx < 8 * S / 4) dst[idx] = src[idx];
        }
    }
    __syncthreads();

    const int w = threadIdx.x >> 5, lane = threadIdx.x & 31;
    const bool has2 = lane < (EV4 - 64);            // lanes 0..10 own slot lane+64
    const float4* __restrict__ ev = (const float4*)emb;
    const int* __restrict__ rid = s_ids + w * S;

    float4 a0 = {0,0,0,0}, a1 = {0,0,0,0}, a2 = {0,0,0,0};
#pragma unroll 4
    for (int t = 0; t < S; ++t) {
        const int base = rid[t] * EV4;              // <= 37.5M, fits int32
        float4 v0 = __ldg(ev + base + lane);
        float4 v1 = __ldg(ev + base + lane + 32);
        a0.x += v0.x; a0.y += v0.y; a0.z += v0.z; a0.w += v0.w;
        a1.x += v1.x; a1.y += v1.y; a1.z += v1.z; a1.w += v1.w;
        if (has2) {
            float4 v2 = __ldg(ev + base + lane + 64);
            a2.x += v2.x; a2.y += v2.y; a2.z += v2.z; a2.w += v2.w;
        }
    }
    const float sc = 1.0f / (float)S;
    float4* p = (float4*)(g_pooled + (b0 + w) * E);
    p[lane]      = make_float4(a0.x*sc, a0.y*sc, a0.z*sc, a0.w*sc);
    p[lane + 32] = make_float4(a1.x*sc, a1.y*sc, a1.z*sc, a1.w*sc);
    if (has2)
        p[lane + 64] = make_float4(a2.x*sc, a2.y*sc, a2.z*sc, a2.w*sc);
}

// ---------------------------------------------------------------------------
// One layer, 2 rows x 20 cols per thread (w loads shared across both rows):
//   acc2[0..9]  : row r0,   cols n0..n0+19 (f32x2 pairs)
//   acc2[10..19]: row r0+1
// Wt pretransposed [300][NW]. PROVEN 2-sync double-buffer pipeline.
// All NT threads must call (uniform).
// ---------------------------------------------------------------------------
__device__ __forceinline__ void gemmT(
    const float* __restrict__ Wt,
    const float* __restrict__ s_a,
    float (*s_w)[TILE_F],
    int r0, int n0, int tid, u64 acc2[20])
{
#pragma unroll
    for (int j = 0; j < 20; ++j) acc2[j] = 0ull;

    const uint32_t sb0 = (uint32_t)__cvta_generic_to_shared(&s_w[0][0]);
    const uint32_t sb1 = (uint32_t)__cvta_generic_to_shared(&s_w[1][0]);

    // prologue: tile 0 -> buf 0
#pragma unroll
    for (int i = 0; i < 7; ++i) {
        const int idx = tid + i * NT;
        if (idx < TILE_F4) cp16(sb0 + idx * 16, Wt + idx * 4);
    }
    cp_commit();

    for (int kt = 0; kt < NKT; ++kt) {
        if (kt + 1 < NKT) {
            const uint32_t dst = ((kt + 1) & 1) ? sb1 : sb0;
            const float* src = Wt + (kt + 1) * TILE_F;
#pragma unroll
            for (int i = 0; i < 7; ++i) {
                const int idx = tid + i * NT;
                if (idx < TILE_F4) cp16(dst + idx * 16, src + idx * 4);
            }
            cp_commit();
            asm volatile("cp.async.wait_group 1;");   // my tile-kt copies done
        } else {
            asm volatile("cp.async.wait_group 0;");
        }
        __syncthreads();              // ALL threads' tile-kt copies visible

        const float* wb = s_w[kt & 1];
        const int kb = kt * BK;
#pragma unroll
        for (int kk = 0; kk < BK; ++kk) {
            const u64 a0 = pack2(s_a[r0 * NPAD + kb + kk]);        // scalar LDS
            const u64 a1 = pack2(s_a[(r0 + 1) * NPAD + kb + kk]);
            // offset (kk*NW + n0) floats = kk*1280 + 80g bytes -> 16B aligned
            const ulonglong2* wr = (const ulonglong2*)(wb + kk * NW + n0);
#pragma unroll
            for (int j = 0; j < 5; ++j) {
                const ulonglong2 wv = wr[j];
                acc2[2*j + 0]      = fma2(a0, wv.x, acc2[2*j + 0]);
                acc2[2*j + 1]      = fma2(a0, wv.y, acc2[2*j + 1]);
                acc2[10 + 2*j + 0] = fma2(a1, wv.x, acc2[10 + 2*j + 0]);
                acc2[10 + 2*j + 1] = fma2(a1, wv.y, acc2[10 + 2*j + 1]);
            }
        }
        __syncthreads();              // buf kt free before next refill
    }
}

// ---------------------------------------------------------------------------
// Kernel 2: 16 rows/CTA, 128 threads, grid 256, 2 rows x 20 cols per thread:
//   relu(relu(pooled W1^T) W2^T) W3^T -> out
// ---------------------------------------------------------------------------
__global__ __launch_bounds__(NT) void gemm_head(
    const float* __restrict__ pooled,
    const float* __restrict__ w3,
    float*       __restrict__ out)
{
    __shared__ float s_w[2][TILE_F];        // 25600 B
    __shared__ float s_a[GM * NPAD];        // 19264 B
    __shared__ float s_w3[TAGS * NW];       //  2560 B  (total 47424 B, static ok)
    float* s_part = &s_w[0][0];             // alias after all cp.async drained

    const int tid = threadIdx.x;
    const int b0  = blockIdx.x * GM;

    // stage pooled rows (vector gmem load, SCALAR smem stores: NPAD rows only
    // 4B-aligned) + padded w3
    {
        const float4* src = (const float4*)(pooled + b0 * E);
#pragma unroll
        for (int i = 0; i < 10; ++i) {
            const int idx = tid + i * NT;        // 0..1199 float4
            if (idx < GM * E / 4) {
                const int m = idx / EV4, s = idx - m * EV4;
                const float4 v = src[idx];
                float* dst = &s_a[m * NPAD + s * 4];
                dst[0] = v.x; dst[1] = v.y; dst[2] = v.z; dst[3] = v.w;
            }
        }
#pragma unroll
        for (int i = 0; i < 5; ++i) {
            const int idx = tid + i * NT;
            if (idx < TAGS * NW) {
                const int t = idx / NW, n = idx % NW;
                s_w3[idx] = (n < E) ? w3[t * E + n] : 0.0f;
            }
        }
    }
    // first __syncthreads inside gemmT (post-wait) fences the staging stores

    const int r0 = (tid & 7) * 2;       // rows r0, r0+1
    const int g  = tid >> 3;            // 0..15
    const int n0 = g * 20;

    u64 acc2[20];

    // layer 1
    gemmT(g_w1t, s_a, s_w, r0, n0, tid, acc2);
    // gemmT ends with __syncthreads: all layer-1 reads of s_a complete
#pragma unroll
    for (int r = 0; r < 2; ++r) {
#pragma unroll
        for (int j = 0; j < 10; ++j) {
            const int n = n0 + 2 * j;
            const u64 v = acc2[r * 10 + j];
            if (n     < E) s_a[(r0 + r) * NPAD + n]     = fmaxf(lo32(v), 0.0f);
            if (n + 1 < E) s_a[(r0 + r) * NPAD + n + 1] = fmaxf(hi32(v), 0.0f);
        }
    }
    // layer 2 (+fused head); first post-wait sync inside orders the h1 stores
    gemmT(g_w2t, s_a, s_w, r0, n0, tid, acc2);

#pragma unroll
    for (int r = 0; r < 2; ++r) {
        float s0 = 0.0f, s1 = 0.0f;
#pragma unroll
        for (int j = 0; j < 10; ++j) {
            const u64 v = acc2[r * 10 + j];
            const float lo = fmaxf(lo32(v), 0.0f);      // pad cols: w=0 -> acc=0
            const float hi = fmaxf(hi32(v), 0.0f);
            s0 = fmaf(lo, s_w3[n0 + 2*j],          s0);
            s0 = fmaf(hi, s_w3[n0 + 2*j + 1],      s0);
            s1 = fmaf(lo, s_w3[NW + n0 + 2*j],     s1);
            s1 = fmaf(hi, s_w3[NW + n0 + 2*j + 1], s1);
        }
        // gemmT's trailing __syncthreads: all compute done, cp.async drained
        s_part[((r0 + r) * 16 + g) * 2 + 0] = s0;
        s_part[((r0 + r) * 16 + g) * 2 + 1] = s1;
    }
    __syncthreads();

    if (tid < GM * TAGS) {
        const int mm = tid >> 1, t = tid & 1;
        float s = 0.0f;
#pragma unroll
        for (int gg = 0; gg < 16; ++gg)
            s += s_part[(mm * 16 + gg) * 2 + t];
        out[(b0 + mm) * TAGS + t] = s;
    }
}

// ---------------------------------------------------------------------------
// Launch
// ---------------------------------------------------------------------------
extern "C" void kernel_launch(void* const* d_in, const int* in_sizes, int n_in,
                              void* d_out, int out_size)
{
    const int*   x   = (const int*)d_in[0];
    const float* emb = (const float*)d_in[1];
    const float* w1  = (const float*)d_in[2];
    const float* w2  = (const float*)d_in[3];
    const float* w3  = (const float*)d_in[4];
    float* out = (float*)d_out;

    float* pooled; cudaGetSymbolAddress((void**)&pooled, g_pooled);

    pool_and_prep<<<PCTA + TCTA, 256>>>(x, emb, w1, w2);
    gemm_head<<<B / GM, NT>>>(pooled, w3, out);
}